// round 1
// baseline (speedup 1.0000x reference)
#include <cuda_runtime.h>
#include <cuda_bf16.h>
#include <math.h>

// Global accumulators (no device allocation allowed).
__device__ float g_pen;   // sum of the three count penalties
__device__ float g_cnt;   // count of (activity != 22)

__global__ void init_accum_kernel() {
    g_pen = 0.0f;
    g_cnt = 0.0f;
}

__global__ __launch_bounds__(256)
void penalty_kernel(const float* __restrict__ x,
                    const float* __restrict__ min_,
                    const float* __restrict__ scale_,
                    long long nrows) {
    const float m2 = __ldg(min_ + 2);
    const float m3 = __ldg(min_ + 3);
    const float is2 = 1.0f / __ldg(scale_ + 2);
    const float is3 = 1.0f / __ldg(scale_ + 3);

    const long long stride = (long long)gridDim.x * blockDim.x;
    const int lane = threadIdx.x & 31;

    float pen = 0.0f;
    float cnt = 0.0f;

    long long i = (long long)blockIdx.x * blockDim.x + threadIdx.x;
    // Warp-uniform loop: all lanes of a warp iterate together; per-row work
    // is predicated on validity so __shfl_down_sync is always full-warp.
    long long warp_base = i - lane;
    for (; warp_base < nrows; warp_base += stride, i += stride) {
        const bool valid = (i < nrows);

        float d = 0.0f, a = 0.0f;
        if (valid) {
            const float2 v = *reinterpret_cast<const float2*>(x + i * 8 + 2);
            d = (v.x - m2) * is2;
            a = (v.y - m3) * is3;
        }

        // Next row's activity: lanes 0..30 get it from lane+1; lane 31 loads it.
        float an = __shfl_down_sync(0xffffffffu, a, 1);
        const bool has_next = valid && (i + 1 < nrows);
        if (lane == 31 && has_next) {
            an = (__ldg(x + (i + 1) * 8 + 3) - m3) * is3;
        }

        if (valid) {
            // device_and_status penalty: NOT (0 <= d <= 252)
            if (d < 0.0f || d > 252.0f) pen += 1.0f;
            // activity out-of-range penalty
            if (a < 0.0f || a > 22.0f) pen += 1.0f;
            // activity count
            if (a != 22.0f) cnt += 1.0f;
        }
        if (has_next) {
            // invalid transition penalty
            const bool cond = (fmodf(a, 2.0f) == 0.0f) && (a < 20.0f);
            if (cond) {
                const bool invalid = (an != a + 1.0f) && (an != 22.0f);
                if (invalid) pen += 1.0f;
            }
        }
    }

    // Warp reduction
    #pragma unroll
    for (int off = 16; off > 0; off >>= 1) {
        pen += __shfl_down_sync(0xffffffffu, pen, off);
        cnt += __shfl_down_sync(0xffffffffu, cnt, off);
    }

    __shared__ float s_pen[8];
    __shared__ float s_cnt[8];
    const int wid = threadIdx.x >> 5;
    if (lane == 0) {
        s_pen[wid] = pen;
        s_cnt[wid] = cnt;
    }
    __syncthreads();

    if (threadIdx.x == 0) {
        float bp = 0.0f, bc = 0.0f;
        const int nwarps = (blockDim.x + 31) >> 5;
        #pragma unroll
        for (int w = 0; w < 8; w++) {
            if (w < nwarps) { bp += s_pen[w]; bc += s_cnt[w]; }
        }
        atomicAdd(&g_pen, bp);
        atomicAdd(&g_cnt, bc);
    }
}

__global__ void finalize_kernel(float* __restrict__ out, int out_size) {
    const float result = g_pen + fabsf(g_cnt - 58.0f);
    for (int i = threadIdx.x; i < out_size; i += blockDim.x) {
        out[i] = result;
    }
}

extern "C" void kernel_launch(void* const* d_in, const int* in_sizes, int n_in,
                              void* d_out, int out_size) {
    const float* x      = (const float*)d_in[0];
    const float* min_   = (const float*)d_in[1];
    const float* scale_ = (const float*)d_in[2];
    float* out = (float*)d_out;

    const long long nrows = (long long)in_sizes[0] / 8;

    // ~8 rows per thread, capped so atomics stay negligible.
    long long blocks_ll = (nrows + 256LL * 8 - 1) / (256LL * 8);
    if (blocks_ll < 1) blocks_ll = 1;
    if (blocks_ll > 4096) blocks_ll = 4096;
    const int blocks = (int)blocks_ll;

    init_accum_kernel<<<1, 1>>>();
    penalty_kernel<<<blocks, 256>>>(x, min_, scale_, nrows);
    finalize_kernel<<<1, 32>>>(out, out_size);
}

// round 2
// speedup vs baseline: 1.0548x; 1.0548x over previous
#include <cuda_runtime.h>
#include <cuda_bf16.h>
#include <math.h>

// Global accumulators + completion ticket (no device allocation allowed).
// Zero-initialized at module load; the last block resets them after each run,
// so every launch (correctness run + every graph replay) sees them at zero.
__device__ float g_pen;
__device__ float g_cnt;
__device__ unsigned int g_done;

__global__ __launch_bounds__(256)
void fused_penalty_kernel(const float* __restrict__ x,
                          const float* __restrict__ min_,
                          const float* __restrict__ scale_,
                          float* __restrict__ out,
                          int out_size,
                          long long nrows,
                          int nblocks) {
    const float m2 = __ldg(min_ + 2);
    const float m3 = __ldg(min_ + 3);
    const float is2 = 1.0f / __ldg(scale_ + 2);
    const float is3 = 1.0f / __ldg(scale_ + 3);

    const long long stride = (long long)gridDim.x * blockDim.x;
    const int lane = threadIdx.x & 31;

    float pen = 0.0f;
    float cnt = 0.0f;

    long long i = (long long)blockIdx.x * blockDim.x + threadIdx.x;
    long long warp_base = i - lane;

    // ---- Unrolled x4 mainloop: all rows valid, all neighbors exist ----
    // Condition warp_base + 4*stride <= nrows guarantees:
    //   max row index = warp_base+31+3*stride < warp_base+4*stride <= nrows
    //   max neighbor  = warp_base+32+3*stride <= warp_base+4*stride (stride>=32)
    while (warp_base + 4 * stride <= nrows) {
        float2 v[4];
        #pragma unroll
        for (int u = 0; u < 4; u++) {
            v[u] = *reinterpret_cast<const float2*>(x + (i + u * stride) * 8 + 2);
        }

        float d[4], a[4], an[4];
        #pragma unroll
        for (int u = 0; u < 4; u++) {
            d[u] = (v[u].x - m2) * is2;
            a[u] = (v[u].y - m3) * is3;
        }

        #pragma unroll
        for (int u = 0; u < 4; u++) {
            an[u] = __shfl_down_sync(0xffffffffu, a[u], 1);
            if (lane == 31) {
                an[u] = (__ldg(x + (i + u * stride + 1) * 8 + 3) - m3) * is3;
            }
        }

        #pragma unroll
        for (int u = 0; u < 4; u++) {
            if (d[u] < 0.0f || d[u] > 252.0f) pen += 1.0f;
            if (a[u] < 0.0f || a[u] > 22.0f)  pen += 1.0f;
            if (a[u] != 22.0f)                cnt += 1.0f;
            const bool cond = (fmodf(a[u], 2.0f) == 0.0f) && (a[u] < 20.0f);
            if (cond && (an[u] != a[u] + 1.0f) && (an[u] != 22.0f)) pen += 1.0f;
        }

        warp_base += 4 * stride;
        i += 4 * stride;
    }

    // ---- Predicated tail loop ----
    for (; warp_base < nrows; warp_base += stride, i += stride) {
        const bool valid = (i < nrows);

        float d = 0.0f, a = 0.0f;
        if (valid) {
            const float2 v = *reinterpret_cast<const float2*>(x + i * 8 + 2);
            d = (v.x - m2) * is2;
            a = (v.y - m3) * is3;
        }

        float an = __shfl_down_sync(0xffffffffu, a, 1);
        const bool has_next = valid && (i + 1 < nrows);
        if (lane == 31 && has_next) {
            an = (__ldg(x + (i + 1) * 8 + 3) - m3) * is3;
        }

        if (valid) {
            if (d < 0.0f || d > 252.0f) pen += 1.0f;
            if (a < 0.0f || a > 22.0f)  pen += 1.0f;
            if (a != 22.0f)             cnt += 1.0f;
        }
        if (has_next) {
            const bool cond = (fmodf(a, 2.0f) == 0.0f) && (a < 20.0f);
            if (cond && (an != a + 1.0f) && (an != 22.0f)) pen += 1.0f;
        }
    }

    // ---- Warp reduction ----
    #pragma unroll
    for (int off = 16; off > 0; off >>= 1) {
        pen += __shfl_down_sync(0xffffffffu, pen, off);
        cnt += __shfl_down_sync(0xffffffffu, cnt, off);
    }

    __shared__ float s_pen[8];
    __shared__ float s_cnt[8];
    const int wid = threadIdx.x >> 5;
    if (lane == 0) {
        s_pen[wid] = pen;
        s_cnt[wid] = cnt;
    }
    __syncthreads();

    if (threadIdx.x == 0) {
        float bp = 0.0f, bc = 0.0f;
        #pragma unroll
        for (int w = 0; w < 8; w++) { bp += s_pen[w]; bc += s_cnt[w]; }

        atomicAdd(&g_pen, bp);
        atomicAdd(&g_cnt, bc);
        __threadfence();

        const unsigned int ticket = atomicAdd(&g_done, 1u);
        if (ticket == (unsigned int)(nblocks - 1)) {
            // All blocks' contributions are in L2 (fence-before-ticket).
            // Read via atomics to bypass any stale L1 state.
            const float p = atomicAdd(&g_pen, 0.0f);
            const float c = atomicAdd(&g_cnt, 0.0f);
            const float result = p + fabsf(c - 58.0f);
            for (int k = 0; k < out_size; k++) out[k] = result;
            // Reset for the next launch/replay.
            g_pen = 0.0f;
            g_cnt = 0.0f;
            __threadfence();
            g_done = 0u;
        }
    }
}

extern "C" void kernel_launch(void* const* d_in, const int* in_sizes, int n_in,
                              void* d_out, int out_size) {
    const float* x      = (const float*)d_in[0];
    const float* min_   = (const float*)d_in[1];
    const float* scale_ = (const float*)d_in[2];
    float* out = (float*)d_out;

    const long long nrows = (long long)in_sizes[0] / 8;

    long long blocks_ll = (nrows + 256LL * 8 - 1) / (256LL * 8);
    if (blocks_ll < 1) blocks_ll = 1;
    if (blocks_ll > 2048) blocks_ll = 2048;
    const int blocks = (int)blocks_ll;

    fused_penalty_kernel<<<blocks, 256>>>(x, min_, scale_, out, out_size,
                                          nrows, blocks);
}

// round 3
// speedup vs baseline: 1.1344x; 1.0755x over previous
#include <cuda_runtime.h>
#include <cuda_bf16.h>
#include <math.h>

// Global accumulators + completion ticket. Zero at module load; the last
// block resets them after each run so every launch/replay sees zeros.
__device__ float g_pen;
__device__ float g_cnt;
__device__ unsigned int g_done;

// Each warp owns a contiguous tile of 256 rows, split into 8 chunks of 32.
// Chunk c covers rows [base+32c, base+32c+32); lane L handles row base+32c+L.
// Neighbor (row+1) activity:
//   lanes 0..30: shfl_down within the chunk
//   lane 31, chunks 0..6: lane 0 of chunk c+1 (register broadcast, no load)
//   lane 31, chunk 7: one 4-byte global load per 256 rows
__global__ __launch_bounds__(256)
void fused_penalty_kernel(const float* __restrict__ x,
                          const float* __restrict__ min_,
                          const float* __restrict__ scale_,
                          float* __restrict__ out,
                          int out_size,
                          long long nrows,
                          int nblocks) {
    const float m2 = __ldg(min_ + 2);
    const float m3 = __ldg(min_ + 3);
    const float is2 = 1.0f / __ldg(scale_ + 2);
    const float is3 = 1.0f / __ldg(scale_ + 3);

    const int lane = threadIdx.x & 31;
    const int wpb = blockDim.x >> 5;
    const long long wid = (long long)blockIdx.x * wpb + (threadIdx.x >> 5);
    const long long nwarps = (long long)gridDim.x * wpb;
    const long long ntiles = (nrows + 255) >> 8;

    float pen = 0.0f;
    float cnt = 0.0f;

    for (long long t = wid; t < ntiles; t += nwarps) {
        const long long base = t << 8;

        if (base + 256 <= nrows) {
            // ---- Full tile: 8 front-batched streaming loads ----
            float2 v[8];
            #pragma unroll
            for (int c = 0; c < 8; c++) {
                v[c] = __ldcs(reinterpret_cast<const float2*>(
                           x + (base + 32LL * c + lane) * 8 + 2));
            }

            // Cross-tile neighbor (row base+256) for lane 31 of chunk 7.
            const bool have_nxt = (base + 256 < nrows);
            float nxt_a = 0.0f;
            if (lane == 31 && have_nxt) {
                nxt_a = (__ldcs(x + (base + 256) * 8 + 3) - m3) * is3;
            }

            float a[8];
            #pragma unroll
            for (int c = 0; c < 8; c++) a[c] = (v[c].y - m3) * is3;

            float an[8];
            #pragma unroll
            for (int c = 0; c < 8; c++)
                an[c] = __shfl_down_sync(0xffffffffu, a[c], 1);
            #pragma unroll
            for (int c = 0; c < 7; c++) {
                const float h = __shfl_sync(0xffffffffu, a[c + 1], 0);
                if (lane == 31) an[c] = h;
            }
            if (lane == 31) an[7] = nxt_a;

            const bool last_ok = (lane != 31) || have_nxt; // chunk-7 guard

            #pragma unroll
            for (int c = 0; c < 8; c++) {
                const float d = (v[c].x - m2) * is2;
                if (d < 0.0f || d > 252.0f)    pen += 1.0f;
                if (a[c] < 0.0f || a[c] > 22.0f) pen += 1.0f;
                if (a[c] != 22.0f)             cnt += 1.0f;

                const bool hn = (c < 7) || last_ok;
                if (hn) {
                    const bool cond = (fmodf(a[c], 2.0f) == 0.0f) && (a[c] < 20.0f);
                    if (cond && (an[c] != a[c] + 1.0f) && (an[c] != 22.0f))
                        pen += 1.0f;
                }
            }
        } else {
            // ---- Partial tail tile: predicated scalar path ----
            #pragma unroll
            for (int c = 0; c < 8; c++) {
                const long long i = base + 32LL * c + lane;
                const bool valid = (i < nrows);
                float d = 0.0f, a0 = 0.0f;
                if (valid) {
                    const float2 v = *reinterpret_cast<const float2*>(x + i * 8 + 2);
                    d  = (v.x - m2) * is2;
                    a0 = (v.y - m3) * is3;
                }
                float an0 = __shfl_down_sync(0xffffffffu, a0, 1);
                const bool hn = valid && (i + 1 < nrows);
                if (lane == 31 && hn) {
                    an0 = (x[(i + 1) * 8 + 3] - m3) * is3;
                }
                if (valid) {
                    if (d < 0.0f || d > 252.0f)   pen += 1.0f;
                    if (a0 < 0.0f || a0 > 22.0f)  pen += 1.0f;
                    if (a0 != 22.0f)              cnt += 1.0f;
                }
                if (hn) {
                    const bool cond = (fmodf(a0, 2.0f) == 0.0f) && (a0 < 20.0f);
                    if (cond && (an0 != a0 + 1.0f) && (an0 != 22.0f))
                        pen += 1.0f;
                }
            }
        }
    }

    // ---- Warp reduction ----
    #pragma unroll
    for (int off = 16; off > 0; off >>= 1) {
        pen += __shfl_down_sync(0xffffffffu, pen, off);
        cnt += __shfl_down_sync(0xffffffffu, cnt, off);
    }

    __shared__ float s_pen[8];
    __shared__ float s_cnt[8];
    const int w = threadIdx.x >> 5;
    if (lane == 0) { s_pen[w] = pen; s_cnt[w] = cnt; }
    __syncthreads();

    if (threadIdx.x == 0) {
        float bp = 0.0f, bc = 0.0f;
        #pragma unroll
        for (int k = 0; k < 8; k++) { bp += s_pen[k]; bc += s_cnt[k]; }

        atomicAdd(&g_pen, bp);
        atomicAdd(&g_cnt, bc);
        __threadfence();

        const unsigned int ticket = atomicAdd(&g_done, 1u);
        if (ticket == (unsigned int)(nblocks - 1)) {
            const float p = atomicAdd(&g_pen, 0.0f);
            const float c = atomicAdd(&g_cnt, 0.0f);
            const float result = p + fabsf(c - 58.0f);
            for (int k = 0; k < out_size; k++) out[k] = result;
            g_pen = 0.0f;
            g_cnt = 0.0f;
            __threadfence();
            g_done = 0u;
        }
    }
}

extern "C" void kernel_launch(void* const* d_in, const int* in_sizes, int n_in,
                              void* d_out, int out_size) {
    const float* x      = (const float*)d_in[0];
    const float* min_   = (const float*)d_in[1];
    const float* scale_ = (const float*)d_in[2];
    float* out = (float*)d_out;

    const long long nrows = (long long)in_sizes[0] / 8;
    const long long ntiles = (nrows + 255) >> 8;

    // 8 warps per block -> one tile per warp when grid covers all tiles.
    long long blocks_ll = (ntiles + 7) / 8;
    if (blocks_ll < 1) blocks_ll = 1;
    if (blocks_ll > 2048) blocks_ll = 2048;
    const int blocks = (int)blocks_ll;

    fused_penalty_kernel<<<blocks, 256>>>(x, min_, scale_, out, out_size,
                                          nrows, blocks);
}